// round 1
// baseline (speedup 1.0000x reference)
#include <cuda_runtime.h>

// filtfilt with butter(4, .2)-style 5-tap IIR, odd extension padlen=15,
// applied independently to 512 rows of length 32768.
//
// Strategy: block-parallel IIR. The filter is stable (max pole magnitude
// ~0.72), so running the recurrence from zero state over WARM=128 samples
// preceding a chunk reproduces the true state to ~1e-19 — each (row, chunk)
// pair is an independent thread. Forward pass writes a __device__ scratch;
// backward pass reads it reversed and writes the cropped output.
// The scale normalize/denormalize in the reference is a per-row linear no-op
// and is skipped.

#define T_LEN     32768
#define PAD       15
#define TEXT      (T_LEN + 2 * PAD)      // 32798
#define ROWSTRIDE 32800                  // padded row stride for scratch
#define MAXROWS   512
#define CH        512                    // samples per chunk
#define NCH       ((TEXT + CH - 1) / CH) // 65
#define WARM      128                    // warm-up samples (pole^128 ~ 1e-19)

__device__ float g_fwd[(size_t)MAXROWS * ROWSTRIDE];

// Odd-extended signal value at extended index t in [0, TEXT).
__device__ __forceinline__ float load_xe(const float* __restrict__ xr, int t) {
    if (t < PAD)          return 2.0f * xr[0]         - xr[PAD - t];
    if (t < T_LEN + PAD)  return xr[t - PAD];
    return 2.0f * xr[T_LEN - 1] - xr[2 * T_LEN + PAD - 2 - t];
}

struct Coef {
    float b0, b1, b2, b3, b4;
    float na1, na2, na3, na4;  // negated a[1..4] (a normalized by a0)
};

__device__ __forceinline__ Coef load_coef(const float* __restrict__ bc,
                                          const float* __restrict__ ac) {
    Coef c;
    float inva0 = 1.0f / ac[0];
    c.b0 = bc[0] * inva0; c.b1 = bc[1] * inva0; c.b2 = bc[2] * inva0;
    c.b3 = bc[3] * inva0; c.b4 = bc[4] * inva0;
    c.na1 = -ac[1] * inva0; c.na2 = -ac[2] * inva0;
    c.na3 = -ac[3] * inva0; c.na4 = -ac[4] * inva0;
    return c;
}

// One DF2-transposed step. Critical recurrence: y <- z0 <- y (2 FMAs).
#define IIR_STEP(xt, y)                                   \
    do {                                                  \
        y  = fmaf(c.b0, (xt), z0);                        \
        z0 = fmaf(c.na1, y, fmaf(c.b1, (xt), z1));        \
        z1 = fmaf(c.na2, y, fmaf(c.b2, (xt), z2));        \
        z2 = fmaf(c.na3, y, fmaf(c.b3, (xt), z3));        \
        z3 = fmaf(c.na4, y, c.b4 * (xt));                 \
    } while (0)

__global__ void fwd_kernel(const float* __restrict__ x,
                           const float* __restrict__ bc,
                           const float* __restrict__ ac,
                           int nrows) {
    int tid = blockIdx.x * blockDim.x + threadIdx.x;
    int row = tid / NCH;
    int ch  = tid - row * NCH;
    if (row >= nrows) return;

    Coef c = load_coef(bc, ac);
    const float* xr = x + (size_t)row * T_LEN;
    float*       yr = g_fwd + (size_t)row * ROWSTRIDE;

    int start = ch * CH;
    int end   = min(start + CH, TEXT);
    int t     = max(0, start - WARM);

    float z0 = 0.f, z1 = 0.f, z2 = 0.f, z3 = 0.f;
    float y;
    // Warm-up: converge the state, discard output.
    for (; t < start; ++t) {
        float xt = load_xe(xr, t);
        IIR_STEP(xt, y);
    }
    // Main: emit.
    #pragma unroll 4
    for (; t < end; ++t) {
        float xt = load_xe(xr, t);
        IIR_STEP(xt, y);
        yr[t] = y;
    }
}

// Backward pass over the forward result (time-reversed), writing the
// cropped, causally-reversed output. s is the reversed index:
// u[s] = y_fwd[TEXT-1-s]; output position t = TEXT-1-s must lie in
// [PAD, T+PAD) -> s in [PAD, TEXT-1-PAD]; out index = TEXT-1-PAD - s.
__global__ void bwd_kernel(const float* __restrict__ bc,
                           const float* __restrict__ ac,
                           float* __restrict__ out,
                           int nrows) {
    int tid = blockIdx.x * blockDim.x + threadIdx.x;
    int row = tid / NCH;
    int ch  = tid - row * NCH;
    if (row >= nrows) return;

    Coef c = load_coef(bc, ac);
    const float* yr = g_fwd + (size_t)row * ROWSTRIDE;
    float*       orow = out + (size_t)row * T_LEN;

    int start = ch * CH;
    int end   = min(start + CH, TEXT);
    int s     = max(0, start - WARM);

    float z0 = 0.f, z1 = 0.f, z2 = 0.f, z3 = 0.f;
    float y;
    for (; s < start; ++s) {
        float xt = yr[TEXT - 1 - s];
        IIR_STEP(xt, y);
    }
    #pragma unroll 4
    for (; s < end; ++s) {
        float xt = yr[TEXT - 1 - s];
        IIR_STEP(xt, y);
        if (s >= PAD && s <= TEXT - 1 - PAD) {
            orow[(TEXT - 1 - PAD) - s] = y;
        }
    }
}

extern "C" void kernel_launch(void* const* d_in, const int* in_sizes, int n_in,
                              void* d_out, int out_size) {
    const float* x  = (const float*)d_in[0];
    const float* bc = (const float*)d_in[1];
    const float* ac = (const float*)d_in[2];
    float* out = (float*)d_out;

    int nrows = in_sizes[0] / T_LEN;  // 32*16 = 512

    int total   = nrows * NCH;
    int threads = 256;
    int blocks  = (total + threads - 1) / threads;

    fwd_kernel<<<blocks, threads>>>(x, bc, ac, nrows);
    bwd_kernel<<<blocks, threads>>>(bc, ac, out, nrows);
}

// round 2
// speedup vs baseline: 1.5729x; 1.5729x over previous
#include <cuda_runtime.h>

// filtfilt (butter(4,0.2)-style 5-tap IIR, odd extension padlen=15) over
// 512 independent rows of T=32768.
//
// R2: warp-cooperative smem tiling. R1 was L1tex-wavefront bound (67% L1,
// 8% DRAM): per-thread chunk streams gave 32 lines per warp LDG. Now each
// warp owns 32 consecutive chunks of a row and stages 32x32 tiles through
// padded shared memory so every global load/store is a single 128B line.
//
// Block-parallel IIR: filter is stable (max |pole| ~0.75); WARM=63 warm-up
// samples from zero state reproduce the true state to ~1e-8.
// The reference's per-row scale/descale is a linear no-op and skipped.

#define T_LEN     32768
#define PAD       15
#define TEXT      (T_LEN + 2 * PAD)   // 32798
#define ROWSTRIDE 32800
#define MAXROWS   512
#define NCH       128                 // chunks per row
#define CH        257                 // NCH*CH = 32896 >= TEXT
#define WARM      63
#define WIN       (WARM + CH)         // 320
#define TILES     (WIN / 32)          // 10
#define WPR       (NCH / 32)          // warps per row = 4
#define BLOCK_WARPS 4

__device__ float g_fwd[(size_t)MAXROWS * ROWSTRIDE];

struct Coef {
    float b0, b1, b2, b3, b4;
    float na1, na2, na3, na4;
};

__device__ __forceinline__ Coef load_coef(const float* __restrict__ bc,
                                          const float* __restrict__ ac) {
    Coef c;
    float inva0 = 1.0f / ac[0];
    c.b0 = bc[0] * inva0; c.b1 = bc[1] * inva0; c.b2 = bc[2] * inva0;
    c.b3 = bc[3] * inva0; c.b4 = bc[4] * inva0;
    c.na1 = -ac[1] * inva0; c.na2 = -ac[2] * inva0;
    c.na3 = -ac[3] * inva0; c.na4 = -ac[4] * inva0;
    return c;
}

// DF2-transposed step; critical chain y <- z0 (2 dependent FMAs).
#define IIR_STEP(xt, y)                                   \
    do {                                                  \
        y  = fmaf(c.b0, (xt), z0);                        \
        z0 = fmaf(c.na1, y, fmaf(c.b1, (xt), z1));        \
        z1 = fmaf(c.na2, y, fmaf(c.b2, (xt), z2));        \
        z2 = fmaf(c.na3, y, fmaf(c.b3, (xt), z3));        \
        z3 = fmaf(c.na4, y, c.b4 * (xt));                 \
    } while (0)

// Odd-extended input at extended index t; 0 outside [0, TEXT) (warm-up /
// tail filler — never emitted).
__device__ __forceinline__ float load_xe_safe(const float* __restrict__ xr, int t) {
    if (t < 0)            return 0.0f;
    if (t < PAD)          return 2.0f * xr[0]         - xr[PAD - t];
    if (t < T_LEN + PAD)  return xr[t - PAD];
    if (t < TEXT)         return 2.0f * xr[T_LEN - 1] - xr[2 * T_LEN + PAD - 2 - t];
    return 0.0f;
}

// Forward-pass scratch read at reversed index s (s=0 is the last fwd sample).
__device__ __forceinline__ float load_rev_safe(const float* __restrict__ yr, int s) {
    if (s < 0 || s >= TEXT) return 0.0f;
    return yr[TEXT - 1 - s];
}

__global__ void __launch_bounds__(BLOCK_WARPS * 32)
fwd_kernel(const float* __restrict__ x,
           const float* __restrict__ bc,
           const float* __restrict__ ac,
           int nrows) {
    int wib  = threadIdx.x >> 5;
    int lane = threadIdx.x & 31;
    int gw   = blockIdx.x * BLOCK_WARPS + wib;
    int row  = gw / WPR;
    int wir  = gw - row * WPR;
    if (row >= nrows) return;

    Coef c = load_coef(bc, ac);
    const float* xr = x + (size_t)row * T_LEN;
    float*       yr = g_fwd + (size_t)row * ROWSTRIDE;

    __shared__ float tile_s[BLOCK_WARPS][32][33];
    float (*sm)[33] = tile_s[wib];

    int c0   = wir * 32;             // first chunk handled by this warp
    int base = c0 * CH - WARM;       // window start of chunk c0

    float z0 = 0.f, z1 = 0.f, z2 = 0.f, z3 = 0.f;
    float y;

    for (int tl = 0; tl < TILES; ++tl) {
        int off = tl * 32;
        // Phase 1: coalesced loads. Step i: lanes fetch 32 consecutive
        // samples of chunk c0+i.
        #pragma unroll 8
        for (int i = 0; i < 32; ++i) {
            int t = base + i * CH + off + lane;
            sm[i][lane] = load_xe_safe(xr, t);
        }
        __syncwarp();
        // Phase 2: each lane advances its private IIR stream 32 steps.
        #pragma unroll
        for (int j = 0; j < 32; ++j) {
            float xt = sm[lane][j];
            IIR_STEP(xt, y);
            sm[lane][j] = y;
        }
        __syncwarp();
        // Phase 3: coalesced stores of emitted samples.
        bool emit = (off + lane) >= WARM;
        #pragma unroll 8
        for (int i = 0; i < 32; ++i) {
            int t = base + i * CH + off + lane;
            if (emit && t < TEXT) yr[t] = sm[i][lane];
        }
        __syncwarp();
    }
}

__global__ void __launch_bounds__(BLOCK_WARPS * 32)
bwd_kernel(const float* __restrict__ bc,
           const float* __restrict__ ac,
           float* __restrict__ out,
           int nrows) {
    int wib  = threadIdx.x >> 5;
    int lane = threadIdx.x & 31;
    int gw   = blockIdx.x * BLOCK_WARPS + wib;
    int row  = gw / WPR;
    int wir  = gw - row * WPR;
    if (row >= nrows) return;

    Coef c = load_coef(bc, ac);
    const float* yr   = g_fwd + (size_t)row * ROWSTRIDE;
    float*       orow = out   + (size_t)row * T_LEN;

    __shared__ float tile_s[BLOCK_WARPS][32][33];
    float (*sm)[33] = tile_s[wib];

    int c0   = wir * 32;
    int base = c0 * CH - WARM;

    float z0 = 0.f, z1 = 0.f, z2 = 0.f, z3 = 0.f;
    float y;

    for (int tl = 0; tl < TILES; ++tl) {
        int off = tl * 32;
        // Phase 1: reversed-time reads; lane addresses are consecutive
        // descending -> still one 128B line per warp load.
        #pragma unroll 8
        for (int i = 0; i < 32; ++i) {
            int s = base + i * CH + off + lane;
            sm[i][lane] = load_rev_safe(yr, s);
        }
        __syncwarp();
        #pragma unroll
        for (int j = 0; j < 32; ++j) {
            float xt = sm[lane][j];
            IIR_STEP(xt, y);
            sm[lane][j] = y;
        }
        __syncwarp();
        // Phase 3: output position t = TEXT-1-s must lie in the cropped
        // range [PAD, T+PAD) -> s in [PAD, TEXT-1-PAD]; out idx descending
        // consecutive -> coalesced.
        bool emit = (off + lane) >= WARM;
        #pragma unroll 8
        for (int i = 0; i < 32; ++i) {
            int s = base + i * CH + off + lane;
            if (emit && s >= PAD && s <= TEXT - 1 - PAD)
                orow[(TEXT - 1 - PAD) - s] = sm[i][lane];
        }
        __syncwarp();
    }
}

extern "C" void kernel_launch(void* const* d_in, const int* in_sizes, int n_in,
                              void* d_out, int out_size) {
    const float* x  = (const float*)d_in[0];
    const float* bc = (const float*)d_in[1];
    const float* ac = (const float*)d_in[2];
    float* out = (float*)d_out;

    int nrows = in_sizes[0] / T_LEN;          // 512
    int total_warps = nrows * WPR;            // 2048
    int blocks = (total_warps + BLOCK_WARPS - 1) / BLOCK_WARPS;
    int threads = BLOCK_WARPS * 32;           // 128

    fwd_kernel<<<blocks, threads>>>(x, bc, ac, nrows);
    bwd_kernel<<<blocks, threads>>>(bc, ac, out, nrows);
}

// round 3
// speedup vs baseline: 2.8818x; 1.8322x over previous
#include <cuda_runtime.h>

// filtfilt (5-tap butter-style IIR, odd extension padlen=15) over 512 rows
// of T=32768.
//
// R3: (1) Direct-Form-I recurrence — critical chain is a single FMA
// (na1*y[n-1]) = 4 cyc/sample vs DF2T's 8; (2) NCH=256 chunks -> 4096 warps
// for latency hiding; (3) branch-free load fast-path for interior warps
// (only first/last warp of a row sees the odd-extension boundary).
// Stable filter: WARM=63 warm-up from zero state -> state error ~1e-8.
// Per-row scale/descale in the reference is a linear no-op, skipped.

#define T_LEN     32768
#define PAD       15
#define TEXT      (T_LEN + 2 * PAD)   // 32798
#define ROWSTRIDE 32800
#define MAXROWS   512
#define NCH       256                 // chunks per row
#define CH        129                 // NCH*CH = 33024 >= TEXT
#define WARM      63
#define WIN       (WARM + CH)         // 192
#define TILES     (WIN / 32)          // 6
#define WPR       (NCH / 32)          // 8 warps per row
#define BLOCK     (WPR * 32)          // 256

__device__ float g_fwd[(size_t)MAXROWS * ROWSTRIDE];

struct Coef {
    float b0, b1, b2, b3, b4;
    float na1, na2, na3, na4;
};

__device__ __forceinline__ Coef load_coef(const float* __restrict__ bc,
                                          const float* __restrict__ ac) {
    Coef c;
    float inva0 = 1.0f / ac[0];
    c.b0 = bc[0] * inva0; c.b1 = bc[1] * inva0; c.b2 = bc[2] * inva0;
    c.b3 = bc[3] * inva0; c.b4 = bc[4] * inva0;
    c.na1 = -ac[1] * inva0; c.na2 = -ac[2] * inva0;
    c.na3 = -ac[3] * inva0; c.na4 = -ac[4] * inva0;
    return c;
}

// DF1 step. Chain: y1 -> y is the LAST fma (4 cyc). Everything else is
// off the critical path (FIR of x history, na2..na4 on older y's).
#define IIR_STEP(xt)                                                   \
    do {                                                               \
        float f = fmaf(c.b0, (xt), fmaf(c.b1, x1,                      \
                  fmaf(c.b2, x2, fmaf(c.b3, x3, c.b4 * x4))));         \
        float s = fmaf(c.na2, y2, fmaf(c.na3, y3,                      \
                  fmaf(c.na4, y4, f)));                                \
        float y = fmaf(c.na1, y1, s);                                  \
        x4 = x3; x3 = x2; x2 = x1; x1 = (xt);                          \
        y4 = y3; y3 = y2; y2 = y1; y1 = y;                             \
    } while (0)

__device__ __forceinline__ float load_xe_safe(const float* __restrict__ xr, int t) {
    if (t < 0)            return 0.0f;
    if (t < PAD)          return 2.0f * xr[0]         - xr[PAD - t];
    if (t < T_LEN + PAD)  return xr[t - PAD];
    if (t < TEXT)         return 2.0f * xr[T_LEN - 1] - xr[2 * T_LEN + PAD - 2 - t];
    return 0.0f;
}

__device__ __forceinline__ float load_rev_safe(const float* __restrict__ yr, int s) {
    if (s < 0 || s >= TEXT) return 0.0f;
    return yr[TEXT - 1 - s];
}

__global__ void __launch_bounds__(BLOCK)
fwd_kernel(const float* __restrict__ x,
           const float* __restrict__ bc,
           const float* __restrict__ ac) {
    int wir  = threadIdx.x >> 5;
    int lane = threadIdx.x & 31;
    int row  = blockIdx.x;

    Coef c = load_coef(bc, ac);
    const float* xr = x + (size_t)row * T_LEN;
    float*       yr = g_fwd + (size_t)row * ROWSTRIDE;

    __shared__ float tile_s[WPR][32][33];
    float (*sm)[33] = tile_s[wir];

    int c0   = wir * 32;
    int base = c0 * CH - WARM;
    // Interior warps never touch the odd-extension boundary nor run past TEXT.
    bool fast = (wir > 0) && (wir < WPR - 1);

    float x1 = 0.f, x2 = 0.f, x3 = 0.f, x4 = 0.f;
    float y1 = 0.f, y2 = 0.f, y3 = 0.f, y4 = 0.f;

    for (int tl = 0; tl < TILES; ++tl) {
        int off = tl * 32;
        if (fast) {
            const float* p = xr + (base - PAD) + off + lane;
            #pragma unroll
            for (int i = 0; i < 32; ++i) sm[i][lane] = p[i * CH];
        } else {
            #pragma unroll 8
            for (int i = 0; i < 32; ++i)
                sm[i][lane] = load_xe_safe(xr, base + i * CH + off + lane);
        }
        __syncwarp();
        #pragma unroll
        for (int j = 0; j < 32; ++j) {
            float xt = sm[lane][j];
            IIR_STEP(xt);
            sm[lane][j] = y1;
        }
        __syncwarp();
        if (tl >= 2) {                 // fully emitted tiles (off >= WARM+1)
            if (fast) {
                float* q = yr + base + off + lane;
                #pragma unroll
                for (int i = 0; i < 32; ++i) q[i * CH] = sm[i][lane];
            } else {
                #pragma unroll 8
                for (int i = 0; i < 32; ++i) {
                    int t = base + i * CH + off + lane;
                    if (t >= 0 && t < TEXT) yr[t] = sm[i][lane];
                }
            }
        } else if (tl == 1) {          // only lane 31 emits (off+lane==63)
            if (lane == 31) {
                #pragma unroll 8
                for (int i = 0; i < 32; ++i) {
                    int t = base + i * CH + off + lane;
                    if (t >= 0 && t < TEXT) yr[t] = sm[i][lane];
                }
            }
        }
        __syncwarp();
    }
}

__global__ void __launch_bounds__(BLOCK)
bwd_kernel(const float* __restrict__ bc,
           const float* __restrict__ ac,
           float* __restrict__ out) {
    int wir  = threadIdx.x >> 5;
    int lane = threadIdx.x & 31;
    int row  = blockIdx.x;

    Coef c = load_coef(bc, ac);
    const float* yr   = g_fwd + (size_t)row * ROWSTRIDE;
    float*       orow = out   + (size_t)row * T_LEN;

    __shared__ float tile_s[WPR][32][33];
    float (*sm)[33] = tile_s[wir];

    int c0   = wir * 32;
    int base = c0 * CH - WARM;
    bool fast = (wir > 0) && (wir < WPR - 1);

    float x1 = 0.f, x2 = 0.f, x3 = 0.f, x4 = 0.f;
    float y1 = 0.f, y2 = 0.f, y3 = 0.f, y4 = 0.f;

    for (int tl = 0; tl < TILES; ++tl) {
        int off = tl * 32;
        if (fast) {
            // u[s] = yr[TEXT-1-s]: descending consecutive, still one line.
            const float* p = yr + (TEXT - 1) - (base + off + lane);
            #pragma unroll
            for (int i = 0; i < 32; ++i) sm[i][lane] = p[-i * CH];
        } else {
            #pragma unroll 8
            for (int i = 0; i < 32; ++i)
                sm[i][lane] = load_rev_safe(yr, base + i * CH + off + lane);
        }
        __syncwarp();
        #pragma unroll
        for (int j = 0; j < 32; ++j) {
            float xt = sm[lane][j];
            IIR_STEP(xt);
            sm[lane][j] = y1;
        }
        __syncwarp();
        // Output: t = TEXT-1-s in crop [PAD, T+PAD) -> s in [PAD, TEXT-1-PAD];
        // out index (TEXT-1-PAD) - s. Interior warps always in range.
        if (tl >= 2) {
            if (fast) {
                float* q = orow + (TEXT - 1 - PAD) - (base + off + lane);
                #pragma unroll
                for (int i = 0; i < 32; ++i) q[-i * CH] = sm[i][lane];
            } else {
                #pragma unroll 8
                for (int i = 0; i < 32; ++i) {
                    int s = base + i * CH + off + lane;
                    if (s >= PAD && s <= TEXT - 1 - PAD)
                        orow[(TEXT - 1 - PAD) - s] = sm[i][lane];
                }
            }
        } else if (tl == 1) {
            if (lane == 31) {
                #pragma unroll 8
                for (int i = 0; i < 32; ++i) {
                    int s = base + i * CH + off + lane;
                    if (s >= PAD && s <= TEXT - 1 - PAD)
                        orow[(TEXT - 1 - PAD) - s] = sm[i][lane];
                }
            }
        }
        __syncwarp();
    }
}

extern "C" void kernel_launch(void* const* d_in, const int* in_sizes, int n_in,
                              void* d_out, int out_size) {
    const float* x  = (const float*)d_in[0];
    const float* bc = (const float*)d_in[1];
    const float* ac = (const float*)d_in[2];
    float* out = (float*)d_out;

    int nrows = in_sizes[0] / T_LEN;  // 512

    fwd_kernel<<<nrows, BLOCK>>>(x, bc, ac);
    bwd_kernel<<<nrows, BLOCK>>>(bc, ac, out);
}